// round 9
// baseline (speedup 1.0000x reference)
#include <cuda_runtime.h>
#include <cuda_fp16.h>
#include <cstdint>
#include <math.h>

#define NTOK 4096
#define HDIM 768
#define FDIM 3072
#define ENUM 6
#define NSLOT (NTOK * 2)

// CTA tile 128(M) x 256(N) x 32(K), warp tile 64x64, fp16, row pitch 40 halfs
#define ROWP 40
#define TA_H (128 * ROWP)            // A tile halfs
#define TB_H (256 * ROWP)            // B tile halfs
#define STG_H (TA_H + TB_H)          // 15360 halfs = 30720 B
#define N_ST 4
#define SMEM_REQ (N_ST * STG_H * 2)  // 122880 B -> 1 CTA/SM

// ---------------- device scratch (no allocations allowed) ----------------
__device__ int    g_counts[ENUM];
__device__ int    g_offsets[ENUM + 1];
__device__ int    g_fill[ENUM];
__device__ int    g_tk_idx[NSLOT];
__device__ float  g_tk_w[NSLOT];
__device__ int    g_slot_tok[NSLOT];
__device__ float  g_slot_w[NSLOT];
__device__ __half g_xh[(size_t)NTOK * HDIM];           // fp16 x
__device__ __half g_hmidh[(size_t)NSLOT * FDIM];       // fp16 mid acts
__device__ __half g_w1h[(size_t)ENUM * FDIM * HDIM];   // w1^T fp16 [E][F][H] = [N][K]
__device__ __half g_w2h[(size_t)ENUM * HDIM * FDIM];   // w2^T fp16 [E][H][F] = [N][K]

// ---------------- helpers ----------------
__device__ __forceinline__ float gelu_exact(float x) {
    return 0.5f * x * (1.0f + erff(x * 0.7071067811865476f));
}
__device__ __forceinline__ uint32_t smem_u32(const void* p) {
    uint32_t a;
    asm("{ .reg .u64 t; cvta.to.shared.u64 t, %1; cvt.u32.u64 %0, t; }" : "=r"(a) : "l"(p));
    return a;
}
__device__ __forceinline__ void cp16(uint32_t dst, const void* src, bool pred) {
    int sz = pred ? 16 : 0;   // src-size 0 => zero-fill
    asm volatile("cp.async.cg.shared.global [%0], [%1], 16, %2;"
                 :: "r"(dst), "l"(src), "r"(sz) : "memory");
}
#define CP_COMMIT() asm volatile("cp.async.commit_group;" ::: "memory")
#define CP_WAIT(n)  asm volatile("cp.async.wait_group %0;" :: "n"(n) : "memory")

__device__ __forceinline__ void mma_f16(float* c, const uint32_t* a, const uint32_t* b) {
    asm volatile(
        "mma.sync.aligned.m16n8k16.row.col.f32.f16.f16.f32 "
        "{%0,%1,%2,%3}, {%4,%5,%6,%7}, {%8,%9}, {%0,%1,%2,%3};\n"
        : "+f"(c[0]), "+f"(c[1]), "+f"(c[2]), "+f"(c[3])
        : "r"(a[0]), "r"(a[1]), "r"(a[2]), "r"(a[3]), "r"(b[0]), "r"(b[1]));
}

// ---------------- kernel: zero output + routing counters ----------------
__global__ void zero_kernel(float* __restrict__ out) {
    int i = blockIdx.x * blockDim.x + threadIdx.x;
    if (i < NTOK * HDIM) out[i] = 0.0f;
    if (i < ENUM) { g_counts[i] = 0; g_fill[i] = 0; }
}

// ---------------- fp16 conversion into DEVICE-SYMBOL scratch ----------------
// (destinations referenced from device code; host-passed __device__ symbols
//  silently hit the host shadow via ATS on GB300 — the R3/R4 bug)
__global__ void conv_x_k(const float* __restrict__ src) {
    int i = blockIdx.x * blockDim.x + threadIdx.x;
    if (i < NTOK * HDIM) g_xh[i] = __float2half_rn(src[i]);
}
// w1 [E][H][F] -> g_w1h [E][F][H]
__global__ void prep_w1_k(const float* __restrict__ src) {
    __shared__ float t[32][33];
    const int e = blockIdx.z;
    const int c0 = blockIdx.x * 32, r0 = blockIdx.y * 32;   // c: F dim, r: H dim
    const int tx = threadIdx.x & 31, ty = threadIdx.x >> 5;
    const float* s = src + (size_t)e * HDIM * FDIM;
    __half* d = g_w1h + (size_t)e * FDIM * HDIM;
#pragma unroll
    for (int i = 0; i < 32; i += 8)
        t[ty + i][tx] = s[(size_t)(r0 + ty + i) * FDIM + c0 + tx];
    __syncthreads();
#pragma unroll
    for (int i = 0; i < 32; i += 8)
        d[(size_t)(c0 + ty + i) * HDIM + r0 + tx] = __float2half_rn(t[tx][ty + i]);
}
// w2 [E][F][H] -> g_w2h [E][H][F]
__global__ void prep_w2_k(const float* __restrict__ src) {
    __shared__ float t[32][33];
    const int e = blockIdx.z;
    const int c0 = blockIdx.x * 32, r0 = blockIdx.y * 32;   // c: H dim, r: F dim
    const int tx = threadIdx.x & 31, ty = threadIdx.x >> 5;
    const float* s = src + (size_t)e * FDIM * HDIM;
    __half* d = g_w2h + (size_t)e * HDIM * FDIM;
#pragma unroll
    for (int i = 0; i < 32; i += 8)
        t[ty + i][tx] = s[(size_t)(r0 + ty + i) * HDIM + c0 + tx];
    __syncthreads();
#pragma unroll
    for (int i = 0; i < 32; i += 8)
        d[(size_t)(c0 + ty + i) * FDIM + r0 + tx] = __float2half_rn(t[tx][ty + i]);
}

// ---------------- gate: scores + top-2 + softmax + counts ----------------
__global__ void gate_kernel(const float* __restrict__ x,
                            const float* __restrict__ gw,
                            const float* __restrict__ gb) {
    const int warp = threadIdx.x >> 5;
    const int lane = threadIdx.x & 31;
    const int tok = blockIdx.x * 8 + warp;
    if (tok >= NTOK) return;

    float acc[ENUM];
#pragma unroll
    for (int e = 0; e < ENUM; ++e) acc[e] = 0.0f;

    const float* xr = x + (size_t)tok * HDIM;
    for (int h = lane; h < HDIM; h += 32) {
        float xv = xr[h];
#pragma unroll
        for (int e = 0; e < ENUM; ++e) acc[e] += xv * gw[h * ENUM + e];
    }
#pragma unroll
    for (int e = 0; e < ENUM; ++e) {
#pragma unroll
        for (int off = 16; off > 0; off >>= 1)
            acc[e] += __shfl_xor_sync(0xffffffffu, acc[e], off);
    }
    if (lane == 0) {
        float best = -1e30f, sec = -1e30f;
        int bi = 0, si = 0;
#pragma unroll
        for (int e = 0; e < ENUM; ++e) {
            float s = acc[e] + gb[e];
            if (s > best) { sec = best; si = bi; best = s; bi = e; }
            else if (s > sec) { sec = s; si = e; }
        }
        float r = expf(sec - best);
        float inv = 1.0f / (1.0f + r);
        g_tk_idx[tok * 2]     = bi;
        g_tk_idx[tok * 2 + 1] = si;
        g_tk_w[tok * 2]       = inv;
        g_tk_w[tok * 2 + 1]   = r * inv;
        atomicAdd(&g_counts[bi], 1);
        atomicAdd(&g_counts[si], 1);
    }
}

__global__ void scan_kernel() {
    if (threadIdx.x == 0 && blockIdx.x == 0) {
        int o = 0;
#pragma unroll
        for (int e = 0; e < ENUM; ++e) { g_offsets[e] = o; o += g_counts[e]; }
        g_offsets[ENUM] = o;
    }
}

__global__ void scatter_kernel() {
    int n = blockIdx.x * blockDim.x + threadIdx.x;
    if (n >= NTOK) return;
#pragma unroll
    for (int k = 0; k < 2; ++k) {
        int e = g_tk_idx[n * 2 + k];
        int pos = g_offsets[e] + atomicAdd(&g_fill[e], 1);
        g_slot_tok[pos] = n;
        g_slot_w[pos]   = g_tk_w[n * 2 + k];
    }
}

// ---------------- grouped GEMM: fp16 mma, CTA 128x256, warp 64x64 ----------
// PHASE 1 (KSPLIT=1): hmidh = half(gelu(gather(xh) @ w1h^T + b1))
// PHASE 2 (KSPLIT=4): out += slot_w * (hmidh @ w2h^T [+ b2 if ks==0]) via atomicAdd
template <int PHASE, int KSPLIT>
__global__ void __launch_bounds__(256, 1) moe_gemm(const float* __restrict__ bias,
                                                   float* __restrict__ out) {
    constexpr int KTOT = (PHASE == 1) ? HDIM : FDIM;
    constexpr int KDIM = KTOT / KSPLIT;
    constexpr int NN   = (PHASE == 1) ? FDIM : HDIM;
    constexpr int KT   = KDIM / 32;

    const int e    = blockIdx.z / KSPLIT;
    const int ks   = blockIdx.z % KSPLIT;
    const int kb   = ks * KDIM;
    const int base = g_offsets[e];
    const int cnt  = g_offsets[e + 1] - base;
    const int m0   = blockIdx.y * 128;
    if (m0 >= cnt) return;
    const int n0 = blockIdx.x * 256;

    const __half* Wh = ((PHASE == 1) ? g_w1h : g_w2h) + (size_t)e * (size_t)NN * KTOT;

    extern __shared__ __half Sh[];   // [N_ST][A 128*ROWP | B 256*ROWP]
    const uint32_t sb = smem_u32(Sh);

    const int tid = threadIdx.x, wid = tid >> 5, lane = tid & 31;

    // cp.async mapping: A row = tid>>1 (128 rows), B rows = tid>>1 and tid>>1+128
    const int crow = tid >> 1;
    const int coff = (tid & 1) * 16;      // halfs offset within 32-half row

    const __half* aptr;                    // A row source (gathered / contiguous)
    {
        int m = m0 + crow;
        if (m < cnt) {
            if (PHASE == 1) aptr = g_xh + (size_t)g_slot_tok[base + m] * HDIM + kb + coff;
            else            aptr = g_hmidh + (size_t)(base + m) * FDIM + kb + coff;
        } else aptr = nullptr;
    }
    const __half* bptr0 = Wh + (size_t)(n0 + crow) * KTOT + kb + coff;
    const __half* bptr1 = Wh + (size_t)(n0 + crow + 128) * KTOT + kb + coff;
    const uint32_t adst = (uint32_t)(crow * ROWP + coff) * 2;         // bytes
    const uint32_t bdst0 = (uint32_t)(TA_H + crow * ROWP + coff) * 2;
    const uint32_t bdst1 = (uint32_t)(TA_H + (crow + 128) * ROWP + coff) * 2;

    auto issue = [&](int b, int k0) {   // k0 in halfs
        uint32_t s0 = sb + (uint32_t)b * STG_H * 2;
        cp16(s0 + adst,       aptr ? (aptr + k0)     : (const __half*)Wh, aptr != nullptr);
        cp16(s0 + adst + 16,  aptr ? (aptr + k0 + 8) : (const __half*)Wh, aptr != nullptr);
        cp16(s0 + bdst0,      bptr0 + k0,     true);
        cp16(s0 + bdst0 + 16, bptr0 + k0 + 8, true);
        cp16(s0 + bdst1,      bptr1 + k0,     true);
        cp16(s0 + bdst1 + 16, bptr1 + k0 + 8, true);
    };

    issue(0, 0);  CP_COMMIT();
    issue(1, 32); CP_COMMIT();
    issue(2, 64); CP_COMMIT();

    const int wm = (wid & 1) * 64;        // 2 M-groups
    const int wn = (wid >> 1) * 64;       // 4 N-groups
    const int g = lane >> 2, t = lane & 3;

    float acc[4][8][4];
#pragma unroll
    for (int mf = 0; mf < 4; ++mf)
#pragma unroll
        for (int nf = 0; nf < 8; ++nf)
#pragma unroll
            for (int c = 0; c < 4; ++c) acc[mf][nf][c] = 0.0f;

    int st = 0;
    for (int kt = 0; kt < KT; ++kt) {
        CP_WAIT(2);                   // oldest outstanding group (stage st) landed
        __syncthreads();              // + all warps done with tile kt-1
        if (kt + 3 < KT) {
            int s3 = st + 3; if (s3 >= N_ST) s3 -= N_ST;
            issue(s3, (kt + 3) * 32); // overwrites stage consumed at iter kt-1: safe
            CP_COMMIT();
        }

        const __half* au = Sh + st * STG_H;
        const __half* bu = au + TA_H;
#pragma unroll
        for (int s = 0; s < 2; ++s) {   // two k16 steps per 32-half tile
            uint32_t af[4][4];
#pragma unroll
            for (int mf = 0; mf < 4; ++mf) {
                const __half* Ap = au + (wm + mf * 16 + g) * ROWP + s * 16 + 2 * t;
                af[mf][0] = *(const uint32_t*)(Ap);
                af[mf][1] = *(const uint32_t*)(Ap + 8 * ROWP);
                af[mf][2] = *(const uint32_t*)(Ap + 8);
                af[mf][3] = *(const uint32_t*)(Ap + 8 * ROWP + 8);
            }
            uint32_t bf[8][2];
#pragma unroll
            for (int nf = 0; nf < 8; ++nf) {
                const __half* Bp = bu + (wn + nf * 8 + g) * ROWP + s * 16 + 2 * t;
                bf[nf][0] = *(const uint32_t*)(Bp);
                bf[nf][1] = *(const uint32_t*)(Bp + 8);
            }
#pragma unroll
            for (int mf = 0; mf < 4; ++mf)
#pragma unroll
                for (int nf = 0; nf < 8; ++nf)
                    mma_f16(acc[mf][nf], af[mf], bf[nf]);
        }
        if (++st == N_ST) st = 0;
    }

    // -------- epilogue --------
    const float* bv = bias + (size_t)e * NN;
    const float bscale = (ks == 0) ? 1.0f : 0.0f;   // bias once per K-split group
#pragma unroll
    for (int mf = 0; mf < 4; ++mf) {
        int rl = wm + mf * 16 + g;
#pragma unroll
        for (int nf = 0; nf < 8; ++nf) {
            int col = n0 + wn + nf * 8 + 2 * t;
            float bb0 = bv[col] * bscale, bb1 = bv[col + 1] * bscale;
#pragma unroll
            for (int half = 0; half < 2; ++half) {
                int mrow = m0 + rl + half * 8;
                if (mrow >= cnt) continue;
                float v0 = acc[mf][nf][half * 2 + 0] + bb0;
                float v1 = acc[mf][nf][half * 2 + 1] + bb1;
                if (PHASE == 1) {
                    size_t o = (size_t)(base + mrow) * FDIM + col;
                    *(__half2*)&g_hmidh[o] =
                        __float22half2_rn(make_float2(gelu_exact(v0), gelu_exact(v1)));
                } else {
                    int slot = base + mrow;
                    int tok = g_slot_tok[slot];
                    float w = g_slot_w[slot];
                    atomicAdd(&out[(size_t)tok * HDIM + col],     w * v0);
                    atomicAdd(&out[(size_t)tok * HDIM + col + 1], w * v1);
                }
            }
        }
    }
}

// ---------------- launch ----------------
extern "C" void kernel_launch(void* const* d_in, const int* in_sizes, int n_in,
                              void* d_out, int out_size) {
    const float* x  = (const float*)d_in[0];
    const float* gw = (const float*)d_in[1];
    const float* gb = (const float*)d_in[2];
    const float* w1 = (const float*)d_in[3];
    const float* b1 = (const float*)d_in[4];
    const float* w2 = (const float*)d_in[5];
    const float* b2 = (const float*)d_in[6];
    float* out = (float*)d_out;

    cudaFuncSetAttribute(moe_gemm<1, 1>, cudaFuncAttributeMaxDynamicSharedMemorySize, SMEM_REQ);
    cudaFuncSetAttribute(moe_gemm<2, 4>, cudaFuncAttributeMaxDynamicSharedMemorySize, SMEM_REQ);

    zero_kernel<<<(NTOK * HDIM + 255) / 256, 256>>>(out);
    gate_kernel<<<NTOK / 8, 256>>>(x, gw, gb);
    scan_kernel<<<1, 32>>>();
    scatter_kernel<<<(NTOK + 255) / 256, 256>>>();

    conv_x_k<<<(NTOK * HDIM + 255) / 256, 256>>>(x);
    prep_w1_k<<<dim3(FDIM / 32, HDIM / 32, ENUM), 256>>>(w1);
    prep_w2_k<<<dim3(HDIM / 32, FDIM / 32, ENUM), 256>>>(w2);

    moe_gemm<1, 1><<<dim3(FDIM / 256, NSLOT / 128, ENUM), 256, SMEM_REQ>>>(b1, nullptr);
    moe_gemm<2, 4><<<dim3(HDIM / 256, NSLOT / 128, ENUM * 4), 256, SMEM_REQ>>>(b2, out);
}

// round 10
// speedup vs baseline: 1.1650x; 1.1650x over previous
#include <cuda_runtime.h>
#include <cuda_fp16.h>
#include <cstdint>
#include <math.h>

#define NTOK 4096
#define HDIM 768
#define FDIM 3072
#define ENUM 6
#define NSLOT (NTOK * 2)

// fp16 tiles: A 128x32 halfs, B 128x32 halfs, row pitch 40 halfs (80B, 16B-aligned)
#define ROWP 40
#define TILE_H (128 * ROWP)          // halfs per tile
#define STG_H  (2 * TILE_H)          // A + B
#define N_ST 4
#define SMEM_REQ (N_ST * STG_H * 2)  // 81920 B -> 2 CTAs/SM (164KB)

// ---------------- device scratch (no allocations allowed) ----------------
__device__ int    g_counts[ENUM];
__device__ int    g_offsets[ENUM + 1];
__device__ int    g_fill[ENUM];
__device__ int    g_tk_idx[NSLOT];
__device__ float  g_tk_w[NSLOT];
__device__ int    g_slot_tok[NSLOT];
__device__ float  g_slot_w[NSLOT];
__device__ __half g_xh[(size_t)NTOK * HDIM];           // fp16 x
__device__ __half g_hmidh[(size_t)NSLOT * FDIM];       // fp16 mid acts
__device__ __half g_w1h[(size_t)ENUM * FDIM * HDIM];   // w1^T fp16 [E][F][H] = [N][K]
__device__ __half g_w2h[(size_t)ENUM * HDIM * FDIM];   // w2^T fp16 [E][H][F] = [N][K]

// ---------------- helpers ----------------
__device__ __forceinline__ float gelu_exact(float x) {
    return 0.5f * x * (1.0f + erff(x * 0.7071067811865476f));
}
__device__ __forceinline__ uint32_t smem_u32(const void* p) {
    uint32_t a;
    asm("{ .reg .u64 t; cvta.to.shared.u64 t, %1; cvt.u32.u64 %0, t; }" : "=r"(a) : "l"(p));
    return a;
}
__device__ __forceinline__ void cp16(uint32_t dst, const void* src, bool pred) {
    int sz = pred ? 16 : 0;   // src-size 0 => zero-fill
    asm volatile("cp.async.cg.shared.global [%0], [%1], 16, %2;"
                 :: "r"(dst), "l"(src), "r"(sz) : "memory");
}
#define CP_COMMIT() asm volatile("cp.async.commit_group;" ::: "memory")
#define CP_WAIT(n)  asm volatile("cp.async.wait_group %0;" :: "n"(n) : "memory")

__device__ __forceinline__ void ldm_x4(uint32_t* r, uint32_t addr) {
    asm volatile("ldmatrix.sync.aligned.m8n8.x4.shared.b16 {%0,%1,%2,%3}, [%4];"
                 : "=r"(r[0]), "=r"(r[1]), "=r"(r[2]), "=r"(r[3]) : "r"(addr));
}

__device__ __forceinline__ void mma_f16(float* c, const uint32_t* a, const uint32_t* b) {
    asm volatile(
        "mma.sync.aligned.m16n8k16.row.col.f32.f16.f16.f32 "
        "{%0,%1,%2,%3}, {%4,%5,%6,%7}, {%8,%9}, {%0,%1,%2,%3};\n"
        : "+f"(c[0]), "+f"(c[1]), "+f"(c[2]), "+f"(c[3])
        : "r"(a[0]), "r"(a[1]), "r"(a[2]), "r"(a[3]), "r"(b[0]), "r"(b[1]));
}

// ---------------- kernel: zero output + routing counters ----------------
__global__ void zero_kernel(float* __restrict__ out) {
    int i = blockIdx.x * blockDim.x + threadIdx.x;
    if (i < NTOK * HDIM) out[i] = 0.0f;
    if (i < ENUM) { g_counts[i] = 0; g_fill[i] = 0; }
}

// ---------------- fp16 conversion into DEVICE-SYMBOL scratch ----------------
// (destinations referenced from device code; host-passed __device__ symbols
//  silently hit the host shadow via ATS on GB300 — the R3/R4 bug)
__global__ void conv_x_k(const float* __restrict__ src) {
    int i = blockIdx.x * blockDim.x + threadIdx.x;
    if (i < NTOK * HDIM) g_xh[i] = __float2half_rn(src[i]);
}
// w1 [E][H][F] -> g_w1h [E][F][H]
__global__ void prep_w1_k(const float* __restrict__ src) {
    __shared__ float t[32][33];
    const int e = blockIdx.z;
    const int c0 = blockIdx.x * 32, r0 = blockIdx.y * 32;   // c: F dim, r: H dim
    const int tx = threadIdx.x & 31, ty = threadIdx.x >> 5;
    const float* s = src + (size_t)e * HDIM * FDIM;
    __half* d = g_w1h + (size_t)e * FDIM * HDIM;
#pragma unroll
    for (int i = 0; i < 32; i += 8)
        t[ty + i][tx] = s[(size_t)(r0 + ty + i) * FDIM + c0 + tx];
    __syncthreads();
#pragma unroll
    for (int i = 0; i < 32; i += 8)
        d[(size_t)(c0 + ty + i) * HDIM + r0 + tx] = __float2half_rn(t[tx][ty + i]);
}
// w2 [E][F][H] -> g_w2h [E][H][F]
__global__ void prep_w2_k(const float* __restrict__ src) {
    __shared__ float t[32][33];
    const int e = blockIdx.z;
    const int c0 = blockIdx.x * 32, r0 = blockIdx.y * 32;   // c: H dim, r: F dim
    const int tx = threadIdx.x & 31, ty = threadIdx.x >> 5;
    const float* s = src + (size_t)e * FDIM * HDIM;
    __half* d = g_w2h + (size_t)e * HDIM * FDIM;
#pragma unroll
    for (int i = 0; i < 32; i += 8)
        t[ty + i][tx] = s[(size_t)(r0 + ty + i) * HDIM + c0 + tx];
    __syncthreads();
#pragma unroll
    for (int i = 0; i < 32; i += 8)
        d[(size_t)(c0 + ty + i) * FDIM + r0 + tx] = __float2half_rn(t[tx][ty + i]);
}

// ---------------- gate: scores + top-2 + softmax + counts ----------------
__global__ void gate_kernel(const float* __restrict__ x,
                            const float* __restrict__ gw,
                            const float* __restrict__ gb) {
    const int warp = threadIdx.x >> 5;
    const int lane = threadIdx.x & 31;
    const int tok = blockIdx.x * 8 + warp;
    if (tok >= NTOK) return;

    float acc[ENUM];
#pragma unroll
    for (int e = 0; e < ENUM; ++e) acc[e] = 0.0f;

    const float* xr = x + (size_t)tok * HDIM;
    for (int h = lane; h < HDIM; h += 32) {
        float xv = xr[h];
#pragma unroll
        for (int e = 0; e < ENUM; ++e) acc[e] += xv * gw[h * ENUM + e];
    }
#pragma unroll
    for (int e = 0; e < ENUM; ++e) {
#pragma unroll
        for (int off = 16; off > 0; off >>= 1)
            acc[e] += __shfl_xor_sync(0xffffffffu, acc[e], off);
    }
    if (lane == 0) {
        float best = -1e30f, sec = -1e30f;
        int bi = 0, si = 0;
#pragma unroll
        for (int e = 0; e < ENUM; ++e) {
            float s = acc[e] + gb[e];
            if (s > best) { sec = best; si = bi; best = s; bi = e; }
            else if (s > sec) { sec = s; si = e; }
        }
        float r = expf(sec - best);
        float inv = 1.0f / (1.0f + r);
        g_tk_idx[tok * 2]     = bi;
        g_tk_idx[tok * 2 + 1] = si;
        g_tk_w[tok * 2]       = inv;
        g_tk_w[tok * 2 + 1]   = r * inv;
        atomicAdd(&g_counts[bi], 1);
        atomicAdd(&g_counts[si], 1);
    }
}

__global__ void scan_kernel() {
    if (threadIdx.x == 0 && blockIdx.x == 0) {
        int o = 0;
#pragma unroll
        for (int e = 0; e < ENUM; ++e) { g_offsets[e] = o; o += g_counts[e]; }
        g_offsets[ENUM] = o;
    }
}

__global__ void scatter_kernel() {
    int n = blockIdx.x * blockDim.x + threadIdx.x;
    if (n >= NTOK) return;
#pragma unroll
    for (int k = 0; k < 2; ++k) {
        int e = g_tk_idx[n * 2 + k];
        int pos = g_offsets[e] + atomicAdd(&g_fill[e], 1);
        g_slot_tok[pos] = n;
        g_slot_w[pos]   = g_tk_w[n * 2 + k];
    }
}

// ---------------- grouped GEMM (fp16 mma m16n8k16 + ldmatrix), 4-stage cp.async ----
// Both A and B live as [row][K] fp16 (B = pre-transposed weights), K-contiguous.
// PHASE 1 (KSPLIT=1): hmidh = half(gelu(gather(xh) @ w1h^T + b1))
// PHASE 2 (KSPLIT=4): out += slot_w * (hmidh @ w2h^T [+ b2 if ks==0]) via atomicAdd
template <int PHASE, int KSPLIT>
__global__ void __launch_bounds__(256, 2) moe_gemm(const float* __restrict__ bias,
                                                   float* __restrict__ out) {
    constexpr int KTOT = (PHASE == 1) ? HDIM : FDIM;
    constexpr int KDIM = KTOT / KSPLIT;
    constexpr int NN   = (PHASE == 1) ? FDIM : HDIM;
    constexpr int KT   = KDIM / 32;

    const int e    = blockIdx.z / KSPLIT;
    const int ks   = blockIdx.z % KSPLIT;
    const int kb   = ks * KDIM;
    const int base = g_offsets[e];
    const int cnt  = g_offsets[e + 1] - base;
    const int m0   = blockIdx.y * 128;
    if (m0 >= cnt) return;
    const int n0 = blockIdx.x * 128;

    const __half* Wh = ((PHASE == 1) ? g_w1h : g_w2h) + (size_t)e * (size_t)NN * KTOT;

    extern __shared__ __half Sh[];   // [N_ST][A 128*ROWP | B 128*ROWP]
    const uint32_t sb = smem_u32(Sh);

    const int tid = threadIdx.x, wid = tid >> 5, lane = tid & 31;

    // cp.async mapping: thread -> (row = tid>>1, 32B half-row chunk = tid&1)
    const int crow = tid >> 1;
    const int coff = (tid & 1) * 16;      // halfs offset within row

    const __half* aptr;                    // A row source (gathered / contiguous)
    {
        int m = m0 + crow;
        if (m < cnt) {
            if (PHASE == 1) aptr = g_xh + (size_t)g_slot_tok[base + m] * HDIM + kb + coff;
            else            aptr = g_hmidh + (size_t)(base + m) * FDIM + kb + coff;
        } else aptr = nullptr;
    }
    const __half* bptr = Wh + (size_t)(n0 + crow) * KTOT + kb + coff;
    const uint32_t sdst = (uint32_t)(crow * ROWP + coff) * 2;   // bytes within tile

    auto issue = [&](int b, int k0) {   // k0 in halfs
        uint32_t a_s = sb + (uint32_t)b * STG_H * 2 + sdst;
        uint32_t b_s = a_s + TILE_H * 2;
        cp16(a_s,      aptr ? (aptr + k0)     : (const __half*)Wh, aptr != nullptr);
        cp16(a_s + 16, aptr ? (aptr + k0 + 8) : (const __half*)Wh, aptr != nullptr);
        cp16(b_s,      bptr + k0, true);
        cp16(b_s + 16, bptr + k0 + 8, true);
    };

    issue(0, 0);  CP_COMMIT();
    issue(1, 32); CP_COMMIT();
    issue(2, 64); CP_COMMIT();

    const int wm = (wid >> 2) * 64;
    const int wn = (wid & 3) * 32;
    const int g = lane >> 2, t = lane & 3;

    // ldmatrix per-lane fragment addresses (byte offsets within a stage)
    // A mf fragment (m16k16): lanes 0-15 -> rows wm+mf*16+(lane&15) @k+0,
    //                         lanes 16-31 -> same rows @k+8
    uint32_t offA[4];
#pragma unroll
    for (int mf = 0; mf < 4; ++mf)
        offA[mf] = (uint32_t)((wm + mf * 16 + (lane & 15)) * ROWP) * 2
                 + ((lane & 16) ? 16u : 0u);
    // B pair j covers nf=2j,2j+1: lanes 0-7 rows wn+j*16+(l&7) @k0, 8-15 same @k8,
    //                             16-23 rows +8 @k0, 24-31 rows +8 @k8
    uint32_t offB[2];
#pragma unroll
    for (int j = 0; j < 2; ++j)
        offB[j] = (uint32_t)(TILE_H + (wn + j * 16 + (lane & 7) + ((lane & 16) ? 8 : 0)) * ROWP) * 2
                + ((lane & 8) ? 16u : 0u);

    float acc[4][4][4];
#pragma unroll
    for (int mf = 0; mf < 4; ++mf)
#pragma unroll
        for (int nf = 0; nf < 4; ++nf)
#pragma unroll
            for (int c = 0; c < 4; ++c) acc[mf][nf][c] = 0.0f;

    int st = 0;
    for (int kt = 0; kt < KT; ++kt) {
        CP_WAIT(2);                   // oldest outstanding group (stage st) landed
        __syncthreads();              // + all warps done with tile kt-1
        if (kt + 3 < KT) {
            int s3 = st + 3; if (s3 >= N_ST) s3 -= N_ST;
            issue(s3, (kt + 3) * 32); // overwrites stage consumed at iter kt-1: safe
            CP_COMMIT();
        }

        const uint32_t stb = sb + (uint32_t)st * STG_H * 2;
#pragma unroll
        for (int s = 0; s < 2; ++s) {   // two k16 steps per 32-half tile
            uint32_t af[4][4];
#pragma unroll
            for (int mf = 0; mf < 4; ++mf)
                ldm_x4(af[mf], stb + offA[mf] + s * 32);
            uint32_t bf4[2][4];
#pragma unroll
            for (int j = 0; j < 2; ++j)
                ldm_x4(bf4[j], stb + offB[j] + s * 32);
#pragma unroll
            for (int mf = 0; mf < 4; ++mf)
#pragma unroll
                for (int nf = 0; nf < 4; ++nf)
                    mma_f16(acc[mf][nf], af[mf], &bf4[nf >> 1][(nf & 1) * 2]);
        }
        if (++st == N_ST) st = 0;
    }

    // -------- epilogue --------
    const float* bv = bias + (size_t)e * NN;
    const float bscale = (ks == 0) ? 1.0f : 0.0f;   // bias once per K-split group
#pragma unroll
    for (int mf = 0; mf < 4; ++mf) {
        int rl = wm + mf * 16 + g;
#pragma unroll
        for (int nf = 0; nf < 4; ++nf) {
            int col = n0 + wn + nf * 8 + 2 * t;
            float bb0 = bv[col] * bscale, bb1 = bv[col + 1] * bscale;
#pragma unroll
            for (int half = 0; half < 2; ++half) {
                int mrow = m0 + rl + half * 8;
                if (mrow >= cnt) continue;
                float v0 = acc[mf][nf][half * 2 + 0] + bb0;
                float v1 = acc[mf][nf][half * 2 + 1] + bb1;
                if (PHASE == 1) {
                    size_t o = (size_t)(base + mrow) * FDIM + col;
                    *(__half2*)&g_hmidh[o] =
                        __float22half2_rn(make_float2(gelu_exact(v0), gelu_exact(v1)));
                } else {
                    int slot = base + mrow;
                    int tok = g_slot_tok[slot];
                    float w = g_slot_w[slot];
                    atomicAdd(&out[(size_t)tok * HDIM + col],     w * v0);
                    atomicAdd(&out[(size_t)tok * HDIM + col + 1], w * v1);
                }
            }
        }
    }
}

// ---------------- launch ----------------
extern "C" void kernel_launch(void* const* d_in, const int* in_sizes, int n_in,
                              void* d_out, int out_size) {
    const float* x  = (const float*)d_in[0];
    const float* gw = (const float*)d_in[1];
    const float* gb = (const float*)d_in[2];
    const float* w1 = (const float*)d_in[3];
    const float* b1 = (const float*)d_in[4];
    const float* w2 = (const float*)d_in[5];
    const float* b2 = (const float*)d_in[6];
    float* out = (float*)d_out;

    cudaFuncSetAttribute(moe_gemm<1, 1>, cudaFuncAttributeMaxDynamicSharedMemorySize, SMEM_REQ);
    cudaFuncSetAttribute(moe_gemm<2, 4>, cudaFuncAttributeMaxDynamicSharedMemorySize, SMEM_REQ);

    zero_kernel<<<(NTOK * HDIM + 255) / 256, 256>>>(out);
    gate_kernel<<<NTOK / 8, 256>>>(x, gw, gb);
    scan_kernel<<<1, 32>>>();
    scatter_kernel<<<(NTOK + 255) / 256, 256>>>();

    conv_x_k<<<(NTOK * HDIM + 255) / 256, 256>>>(x);
    prep_w1_k<<<dim3(FDIM / 32, HDIM / 32, ENUM), 256>>>(w1);
    prep_w2_k<<<dim3(HDIM / 32, FDIM / 32, ENUM), 256>>>(w2);

    moe_gemm<1, 1><<<dim3(FDIM / 128, NSLOT / 128, ENUM), 256, SMEM_REQ>>>(b1, nullptr);
    moe_gemm<2, 4><<<dim3(HDIM / 128, NSLOT / 128, ENUM * 4), 256, SMEM_REQ>>>(b2, out);
}

// round 11
// speedup vs baseline: 1.2099x; 1.0386x over previous
#include <cuda_runtime.h>
#include <cuda_fp16.h>
#include <cstdint>
#include <math.h>

#define NTOK 4096
#define HDIM 768
#define FDIM 3072
#define ENUM 6
#define EBKT 4096                    // per-expert bucket capacity (max tokens)

// fp16 tiles: A 128x32 halfs, B 128x32 halfs, row pitch 40 halfs (80B, 16B-aligned)
#define ROWP 40
#define TILE_H (128 * ROWP)          // halfs per tile
#define STG_H  (2 * TILE_H)          // A + B
#define N_ST 4
#define SMEM_REQ (N_ST * STG_H * 2)  // 81920 B -> 2 CTAs/SM (164KB)

// ---------------- device scratch (no allocations allowed) ----------------
__device__ int    g_counts[ENUM];
__device__ int    g_slot_tok[ENUM * EBKT];
__device__ float  g_slot_w[ENUM * EBKT];
__device__ __half g_xh[(size_t)NTOK * HDIM];                 // fp16 x
__device__ __half g_hmidh[(size_t)ENUM * EBKT * FDIM];       // fp16 mid acts (bucketed)
__device__ __half g_w1h[(size_t)ENUM * FDIM * HDIM];         // w1^T fp16 [E][F][H] = [N][K]
__device__ __half g_w2h[(size_t)ENUM * HDIM * FDIM];         // w2^T fp16 [E][H][F] = [N][K]

// ---------------- helpers ----------------
__device__ __forceinline__ float gelu_exact(float x) {
    return 0.5f * x * (1.0f + erff(x * 0.7071067811865476f));
}
__device__ __forceinline__ uint32_t smem_u32(const void* p) {
    uint32_t a;
    asm("{ .reg .u64 t; cvta.to.shared.u64 t, %1; cvt.u32.u64 %0, t; }" : "=r"(a) : "l"(p));
    return a;
}
__device__ __forceinline__ void cp16(uint32_t dst, const void* src, bool pred) {
    int sz = pred ? 16 : 0;   // src-size 0 => zero-fill
    asm volatile("cp.async.cg.shared.global [%0], [%1], 16, %2;"
                 :: "r"(dst), "l"(src), "r"(sz) : "memory");
}
#define CP_COMMIT() asm volatile("cp.async.commit_group;" ::: "memory")
#define CP_WAIT(n)  asm volatile("cp.async.wait_group %0;" :: "n"(n) : "memory")

__device__ __forceinline__ void ldm_x4(uint32_t* r, uint32_t addr) {
    asm volatile("ldmatrix.sync.aligned.m8n8.x4.shared.b16 {%0,%1,%2,%3}, [%4];"
                 : "=r"(r[0]), "=r"(r[1]), "=r"(r[2]), "=r"(r[3]) : "r"(addr));
}

__device__ __forceinline__ void mma_f16(float* c, const uint32_t* a, const uint32_t* b) {
    asm volatile(
        "mma.sync.aligned.m16n8k16.row.col.f32.f16.f16.f32 "
        "{%0,%1,%2,%3}, {%4,%5,%6,%7}, {%8,%9}, {%0,%1,%2,%3};\n"
        : "+f"(c[0]), "+f"(c[1]), "+f"(c[2]), "+f"(c[3])
        : "r"(a[0]), "r"(a[1]), "r"(a[2]), "r"(a[3]), "r"(b[0]), "r"(b[1]));
}

// ---------------- weight prep (+counter zero rides launch #1) ----------------
// w1 [E][H][F] -> g_w1h [E][F][H]
__global__ void prep_w1_k(const float* __restrict__ src) {
    if (blockIdx.x == 0 && blockIdx.y == 0 && blockIdx.z == 0 && threadIdx.x < ENUM)
        g_counts[threadIdx.x] = 0;
    __shared__ float t[32][33];
    const int e = blockIdx.z;
    const int c0 = blockIdx.x * 32, r0 = blockIdx.y * 32;   // c: F dim, r: H dim
    const int tx = threadIdx.x & 31, ty = threadIdx.x >> 5;
    const float* s = src + (size_t)e * HDIM * FDIM;
    __half* d = g_w1h + (size_t)e * FDIM * HDIM;
#pragma unroll
    for (int i = 0; i < 32; i += 8)
        t[ty + i][tx] = s[(size_t)(r0 + ty + i) * FDIM + c0 + tx];
    __syncthreads();
#pragma unroll
    for (int i = 0; i < 32; i += 8)
        d[(size_t)(c0 + ty + i) * HDIM + r0 + tx] = __float2half_rn(t[tx][ty + i]);
}
// w2 [E][F][H] -> g_w2h [E][H][F]
__global__ void prep_w2_k(const float* __restrict__ src) {
    __shared__ float t[32][33];
    const int e = blockIdx.z;
    const int c0 = blockIdx.x * 32, r0 = blockIdx.y * 32;   // c: H dim, r: F dim
    const int tx = threadIdx.x & 31, ty = threadIdx.x >> 5;
    const float* s = src + (size_t)e * FDIM * HDIM;
    __half* d = g_w2h + (size_t)e * HDIM * FDIM;
#pragma unroll
    for (int i = 0; i < 32; i += 8)
        t[ty + i][tx] = s[(size_t)(r0 + ty + i) * HDIM + c0 + tx];
    __syncthreads();
#pragma unroll
    for (int i = 0; i < 32; i += 8)
        d[(size_t)(c0 + ty + i) * FDIM + r0 + tx] = __float2half_rn(t[tx][ty + i]);
}

// ---------------- fp16 conversion of x ----------------
__global__ void conv_x_k(const float* __restrict__ src) {
    int i = blockIdx.x * blockDim.x + threadIdx.x;
    if (i < NTOK * HDIM) g_xh[i] = __float2half_rn(src[i]);
}

// ---------------- gate: zero out rows + scores + top-2 + direct scatter ------
__global__ void gate_kernel(const float* __restrict__ x,
                            const float* __restrict__ gw,
                            const float* __restrict__ gb,
                            float* __restrict__ out) {
    const int tid  = threadIdx.x;
    const int warp = tid >> 5;
    const int lane = tid & 31;
    const int tokbase = blockIdx.x * 8;
    const int tok = tokbase + warp;

    // zero the 8 output rows owned by this block (8*768 floats = 1536 float4)
    float4* oz = (float4*)(out + (size_t)tokbase * HDIM);
#pragma unroll
    for (int i = 0; i < 6; ++i)
        oz[tid + 256 * i] = make_float4(0.f, 0.f, 0.f, 0.f);

    float acc[ENUM];
#pragma unroll
    for (int e = 0; e < ENUM; ++e) acc[e] = 0.0f;

    const float* xr = x + (size_t)tok * HDIM;
    for (int h = lane; h < HDIM; h += 32) {
        float xv = xr[h];
#pragma unroll
        for (int e = 0; e < ENUM; ++e) acc[e] += xv * gw[h * ENUM + e];
    }
#pragma unroll
    for (int e = 0; e < ENUM; ++e) {
#pragma unroll
        for (int off = 16; off > 0; off >>= 1)
            acc[e] += __shfl_xor_sync(0xffffffffu, acc[e], off);
    }
    if (lane == 0) {
        float best = -1e30f, sec = -1e30f;
        int bi = 0, si = 0;
#pragma unroll
        for (int e = 0; e < ENUM; ++e) {
            float s = acc[e] + gb[e];
            if (s > best) { sec = best; si = bi; best = s; bi = e; }
            else if (s > sec) { sec = s; si = e; }
        }
        float r = expf(sec - best);
        float inv = 1.0f / (1.0f + r);
        int p0 = atomicAdd(&g_counts[bi], 1);
        g_slot_tok[bi * EBKT + p0] = tok;
        g_slot_w[bi * EBKT + p0]   = inv;
        int p1 = atomicAdd(&g_counts[si], 1);
        g_slot_tok[si * EBKT + p1] = tok;
        g_slot_w[si * EBKT + p1]   = r * inv;
    }
}

// ---------------- grouped GEMM (fp16 mma m16n8k16 + ldmatrix), 4-stage cp.async ----
// PHASE 1 (KSPLIT=1): hmidh = half(gelu(gather(xh) @ w1h^T + b1))
// PHASE 2 (KSPLIT=2): out += slot_w * (hmidh @ w2h^T [+ b2 if ks==0]) via atomicAdd
template <int PHASE, int KSPLIT>
__global__ void __launch_bounds__(256, 2) moe_gemm(const float* __restrict__ bias,
                                                   float* __restrict__ out) {
    constexpr int KTOT = (PHASE == 1) ? HDIM : FDIM;
    constexpr int KDIM = KTOT / KSPLIT;
    constexpr int NN   = (PHASE == 1) ? FDIM : HDIM;
    constexpr int KT   = KDIM / 32;

    const int e    = blockIdx.z / KSPLIT;
    const int ks   = blockIdx.z % KSPLIT;
    const int kb   = ks * KDIM;
    const int base = e * EBKT;
    const int cnt  = g_counts[e];
    const int m0   = blockIdx.y * 128;
    if (m0 >= cnt) return;
    const int n0 = blockIdx.x * 128;

    const __half* Wh = ((PHASE == 1) ? g_w1h : g_w2h) + (size_t)e * (size_t)NN * KTOT;

    extern __shared__ __half Sh[];   // [N_ST][A 128*ROWP | B 128*ROWP]
    const uint32_t sb = smem_u32(Sh);

    const int tid = threadIdx.x, wid = tid >> 5, lane = tid & 31;

    // cp.async mapping: thread -> (row = tid>>1, 32B half-row chunk = tid&1)
    const int crow = tid >> 1;
    const int coff = (tid & 1) * 16;      // halfs offset within row

    const __half* aptr;                    // A row source (gathered / contiguous)
    {
        int m = m0 + crow;
        if (m < cnt) {
            if (PHASE == 1) aptr = g_xh + (size_t)g_slot_tok[base + m] * HDIM + kb + coff;
            else            aptr = g_hmidh + (size_t)(base + m) * FDIM + kb + coff;
        } else aptr = nullptr;
    }
    const __half* bptr = Wh + (size_t)(n0 + crow) * KTOT + kb + coff;
    const uint32_t sdst = (uint32_t)(crow * ROWP + coff) * 2;   // bytes within tile

    auto issue = [&](int b, int k0) {   // k0 in halfs
        uint32_t a_s = sb + (uint32_t)b * STG_H * 2 + sdst;
        uint32_t b_s = a_s + TILE_H * 2;
        cp16(a_s,      aptr ? (aptr + k0)     : (const __half*)Wh, aptr != nullptr);
        cp16(a_s + 16, aptr ? (aptr + k0 + 8) : (const __half*)Wh, aptr != nullptr);
        cp16(b_s,      bptr + k0, true);
        cp16(b_s + 16, bptr + k0 + 8, true);
    };

    issue(0, 0);  CP_COMMIT();
    issue(1, 32); CP_COMMIT();
    issue(2, 64); CP_COMMIT();

    const int wm = (wid >> 2) * 64;
    const int wn = (wid & 3) * 32;
    const int g = lane >> 2, t = lane & 3;

    // ldmatrix per-lane fragment addresses (byte offsets within a stage)
    uint32_t offA[4];
#pragma unroll
    for (int mf = 0; mf < 4; ++mf)
        offA[mf] = (uint32_t)((wm + mf * 16 + (lane & 15)) * ROWP) * 2
                 + ((lane & 16) ? 16u : 0u);
    uint32_t offB[2];
#pragma unroll
    for (int j = 0; j < 2; ++j)
        offB[j] = (uint32_t)(TILE_H + (wn + j * 16 + (lane & 7) + ((lane & 16) ? 8 : 0)) * ROWP) * 2
                + ((lane & 8) ? 16u : 0u);

    float acc[4][4][4];
#pragma unroll
    for (int mf = 0; mf < 4; ++mf)
#pragma unroll
        for (int nf = 0; nf < 4; ++nf)
#pragma unroll
            for (int c = 0; c < 4; ++c) acc[mf][nf][c] = 0.0f;

    int st = 0;
    for (int kt = 0; kt < KT; ++kt) {
        CP_WAIT(2);                   // oldest outstanding group (stage st) landed
        __syncthreads();              // + all warps done with tile kt-1
        if (kt + 3 < KT) {
            int s3 = st + 3; if (s3 >= N_ST) s3 -= N_ST;
            issue(s3, (kt + 3) * 32); // overwrites stage consumed at iter kt-1: safe
            CP_COMMIT();
        }

        const uint32_t stb = sb + (uint32_t)st * STG_H * 2;
#pragma unroll
        for (int s = 0; s < 2; ++s) {   // two k16 steps per 32-half tile
            uint32_t af[4][4];
#pragma unroll
            for (int mf = 0; mf < 4; ++mf)
                ldm_x4(af[mf], stb + offA[mf] + s * 32);
            uint32_t bf4[2][4];
#pragma unroll
            for (int j = 0; j < 2; ++j)
                ldm_x4(bf4[j], stb + offB[j] + s * 32);
#pragma unroll
            for (int mf = 0; mf < 4; ++mf)
#pragma unroll
                for (int nf = 0; nf < 4; ++nf)
                    mma_f16(acc[mf][nf], af[mf], &bf4[nf >> 1][(nf & 1) * 2]);
        }
        if (++st == N_ST) st = 0;
    }

    // -------- epilogue --------
    const float* bv = bias + (size_t)e * NN;
    const float bscale = (ks == 0) ? 1.0f : 0.0f;   // bias once per K-split group
#pragma unroll
    for (int mf = 0; mf < 4; ++mf) {
        int rl = wm + mf * 16 + g;
#pragma unroll
        for (int nf = 0; nf < 4; ++nf) {
            int col = n0 + wn + nf * 8 + 2 * t;
            float bb0 = bv[col] * bscale, bb1 = bv[col + 1] * bscale;
#pragma unroll
            for (int half = 0; half < 2; ++half) {
                int mrow = m0 + rl + half * 8;
                if (mrow >= cnt) continue;
                float v0 = acc[mf][nf][half * 2 + 0] + bb0;
                float v1 = acc[mf][nf][half * 2 + 1] + bb1;
                if (PHASE == 1) {
                    size_t o = (size_t)(base + mrow) * FDIM + col;
                    *(__half2*)&g_hmidh[o] =
                        __float22half2_rn(make_float2(gelu_exact(v0), gelu_exact(v1)));
                } else {
                    int slot = base + mrow;
                    int tok = g_slot_tok[slot];
                    float w = g_slot_w[slot];
                    atomicAdd(&out[(size_t)tok * HDIM + col],     w * v0);
                    atomicAdd(&out[(size_t)tok * HDIM + col + 1], w * v1);
                }
            }
        }
    }
}

// ---------------- launch ----------------
extern "C" void kernel_launch(void* const* d_in, const int* in_sizes, int n_in,
                              void* d_out, int out_size) {
    const float* x  = (const float*)d_in[0];
    const float* gw = (const float*)d_in[1];
    const float* gb = (const float*)d_in[2];
    const float* w1 = (const float*)d_in[3];
    const float* b1 = (const float*)d_in[4];
    const float* w2 = (const float*)d_in[5];
    const float* b2 = (const float*)d_in[6];
    float* out = (float*)d_out;

    cudaFuncSetAttribute(moe_gemm<1, 1>, cudaFuncAttributeMaxDynamicSharedMemorySize, SMEM_REQ);
    cudaFuncSetAttribute(moe_gemm<2, 2>, cudaFuncAttributeMaxDynamicSharedMemorySize, SMEM_REQ);

    // order chosen so moe_gemm<1> is the 4th launch (profiler capture slot)
    prep_w1_k<<<dim3(FDIM / 32, HDIM / 32, ENUM), 256>>>(w1);
    gate_kernel<<<NTOK / 8, 256>>>(x, gw, gb, out);
    conv_x_k<<<(NTOK * HDIM + 255) / 256, 256>>>(x);
    moe_gemm<1, 1><<<dim3(FDIM / 128, EBKT / 128, ENUM), 256, SMEM_REQ>>>(b1, nullptr);
    prep_w2_k<<<dim3(HDIM / 32, FDIM / 32, ENUM), 256>>>(w2);
    moe_gemm<2, 2><<<dim3(HDIM / 128, EBKT / 128, ENUM * 2), 256, SMEM_REQ>>>(b2, out);
}